// round 6
// baseline (speedup 1.0000x reference)
#include <cuda_runtime.h>
#include <stdint.h>

#define NNODES   100000
#define NGRAPHS  128
#define HDIM     256

// Scratch (no allocation allowed)
__device__ float d_agg[NNODES];
__device__ int   d_starts[NGRAPHS + 1];
__device__ float d_P;        // sum_{w_k>0} W_out[k]*W_l[k]
__device__ float d_Nn;       // sum_{w_k<0} W_out[k]*W_l[k]
__device__ int   d_blzero;   // 1 if all b_l == 0 -> 2-slope fast path valid
__device__ int   d_ctr;      // completion counter (zeroed per launch by memset)

__device__ __forceinline__ float ldcg(const float* p) {
    float v;
    asm volatile("ld.global.cg.f32 %0, [%1];" : "=f"(v) : "l"(p));
    return v;
}

// ---------------------------------------------------------------------------
// Single fused kernel:
//   blocks [0, edgeBlocks)            : edge scatter-add agg[dst] += x[src]
//   blocks [.., +bndBlocks)           : boundary detect on sorted batch
//   block  [.., +1)                   : setup (b_l==0 flag, P, Nn)
//   blocks [nonPool, nonPool+NGRAPHS) : pool — spin until all above done,
//                                       then mean-pool + output (1 blk/graph)
// Pool blocks sit at the grid tail -> scheduled in the last wave; at most 128
// spinners vs ~1184 concurrent block slots, so no scheduling deadlock.
// ---------------------------------------------------------------------------
__global__ void fused_kernel(const int* __restrict__ ei,
                             const float* __restrict__ x,
                             const int* __restrict__ batch,
                             const float* __restrict__ W_l,
                             const float* __restrict__ b_l,
                             const float* __restrict__ W_out,
                             const float* __restrict__ b_out,
                             float* __restrict__ out,
                             int E, int N, int edgeBlocks, int bndBlocks) {
    const int bid = (int)blockIdx.x;
    const int nonPool = edgeBlocks + bndBlocks + 1;

    if (bid < edgeBlocks) {
        // ---- edge scatter: 8 edges/thread ----
        int t = bid * blockDim.x + threadIdx.x;
        int i = t << 3;
        if (i + 7 < E) {
            const int4* sp = reinterpret_cast<const int4*>(ei + i);
            const int4* dp = reinterpret_cast<const int4*>(ei + E + i);
            int4 s0 = __ldg(sp);
            int4 s1 = __ldg(sp + 1);
            int4 d0 = __ldg(dp);
            int4 d1 = __ldg(dp + 1);
            float v0 = __ldg(x + s0.x);
            float v1 = __ldg(x + s0.y);
            float v2 = __ldg(x + s0.z);
            float v3 = __ldg(x + s0.w);
            float v4 = __ldg(x + s1.x);
            float v5 = __ldg(x + s1.y);
            float v6 = __ldg(x + s1.z);
            float v7 = __ldg(x + s1.w);
            atomicAdd(&d_agg[d0.x], v0);
            atomicAdd(&d_agg[d0.y], v1);
            atomicAdd(&d_agg[d0.z], v2);
            atomicAdd(&d_agg[d0.w], v3);
            atomicAdd(&d_agg[d1.x], v4);
            atomicAdd(&d_agg[d1.y], v5);
            atomicAdd(&d_agg[d1.z], v6);
            atomicAdd(&d_agg[d1.w], v7);
        } else if (i < E) {
            for (int e = i; e < E; e++)
                atomicAdd(&d_agg[ei[E + e]], __ldg(x + ei[e]));
        }
        __threadfence();
        __syncthreads();
        if (threadIdx.x == 0) atomicAdd(&d_ctr, 1);
    } else if (bid < edgeBlocks + bndBlocks) {
        // ---- boundary detection, 4 nodes/thread ----
        int t    = (bid - edgeBlocks) * blockDim.x + threadIdx.x;
        int base = t << 2;
        if (base < N) {
            int b0, b1, b2, b3;
            if (base + 3 < N) {
                int4 v = __ldg(reinterpret_cast<const int4*>(batch + base));
                b0 = v.x; b1 = v.y; b2 = v.z; b3 = v.w;
            } else {
                b0 = batch[base];
                b1 = (base + 1 < N) ? batch[base + 1] : b0;
                b2 = (base + 2 < N) ? batch[base + 2] : b1;
                b3 = (base + 3 < N) ? batch[base + 3] : b2;
            }
            int prev = (base == 0) ? -1 : __ldg(batch + base - 1);
            #pragma unroll
            for (int e = 0; e < 4; e++) {
                int idx = base + e;
                int b = (e == 0) ? b0 : (e == 1) ? b1 : (e == 2) ? b2 : b3;
                if (idx < N) {
                    for (int g = prev + 1; g <= b; g++) d_starts[g] = idx;
                    prev = b;
                    if (idx == N - 1)
                        for (int g = b + 1; g <= NGRAPHS; g++) d_starts[g] = N;
                }
            }
        }
        __threadfence();
        __syncthreads();
        if (threadIdx.x == 0) atomicAdd(&d_ctr, 1);
    } else if (bid < nonPool) {
        // ---- setup block: b_l==0 flag + 2-slope constants ----
        const int k = threadIdx.x;
        const float b  = b_l[k];
        const float w  = W_l[k];
        const float wo = W_out[k];
        const int allz = __syncthreads_and(b == 0.0f);
        float p = (w > 0.0f) ? wo * w : 0.0f;
        float n = (w < 0.0f) ? wo * w : 0.0f;
        #pragma unroll
        for (int off = 16; off; off >>= 1) {
            p += __shfl_xor_sync(0xffffffffu, p, off);
            n += __shfl_xor_sync(0xffffffffu, n, off);
        }
        __shared__ float sp8[8], sn8[8];
        const int wid = k >> 5, lid = k & 31;
        if (lid == 0) { sp8[wid] = p; sn8[wid] = n; }
        __syncthreads();
        if (k == 0) {
            float P = 0.0f, Nn = 0.0f;
            #pragma unroll
            for (int wI = 0; wI < 8; wI++) { P += sp8[wI]; Nn += sn8[wI]; }
            d_P = P; d_Nn = Nn; d_blzero = allz;
            __threadfence();
            atomicAdd(&d_ctr, 1);
        }
    } else {
        // ---- pool block for graph g: wait for all producers, then pool ----
        const int g = bid - nonPool;
        const int t = threadIdx.x;
        if (t == 0) {
            while (atomicAdd(&d_ctr, 0) < nonPool) __nanosleep(100);
        }
        __syncthreads();
        __threadfence();

        const int start = d_starts[g];
        const int end   = d_starts[g + 1];
        const int len   = end - start;
        const float cnt = fmaxf((float)len, 1.0f);

        __shared__ float red0[8], red1[8];
        const int wid = t >> 5, lid = t & 31;

        if (d_blzero) {
            float sp = 0.0f, sn = 0.0f;
            #pragma unroll 4
            for (int i = start + t; i < end; i += HDIM) {
                float v = ldcg(&d_agg[i]);
                sp += fmaxf(v, 0.0f);
                sn += fminf(v, 0.0f);
            }
            #pragma unroll
            for (int off = 16; off; off >>= 1) {
                sp += __shfl_xor_sync(0xffffffffu, sp, off);
                sn += __shfl_xor_sync(0xffffffffu, sn, off);
            }
            if (lid == 0) { red0[wid] = sp; red1[wid] = sn; }
            __syncthreads();
            if (t == 0) {
                float SP = 0.0f, SN = 0.0f;
                #pragma unroll
                for (int wI = 0; wI < 8; wI++) { SP += red0[wI]; SN += red1[wI]; }
                out[g] = fmaxf((d_P * SP + d_Nn * SN) / cnt + b_out[0], 0.0f);
            }
            return;
        }

        // exact slow path (general b_l): one thread per feature
        const float w = W_l[t];
        const float b = b_l[t];
        float acc = 0.0f;
        __shared__ float sa[HDIM];
        for (int base = start; base < end; base += HDIM) {
            int n = min(HDIM, end - base);
            __syncthreads();
            if (t < n) sa[t] = ldcg(&d_agg[base + t]);
            __syncthreads();
            float a0 = 0.f, a1 = 0.f, a2 = 0.f, a3 = 0.f;
            int j = 0;
            for (; j + 3 < n; j += 4) {
                a0 += fmaxf(fmaf(sa[j],     w, b), 0.0f);
                a1 += fmaxf(fmaf(sa[j + 1], w, b), 0.0f);
                a2 += fmaxf(fmaf(sa[j + 2], w, b), 0.0f);
                a3 += fmaxf(fmaf(sa[j + 3], w, b), 0.0f);
            }
            for (; j < n; j++)
                a0 += fmaxf(fmaf(sa[j], w, b), 0.0f);
            acc += (a0 + a1) + (a2 + a3);
        }
        float val = acc * W_out[t] / cnt;
        #pragma unroll
        for (int off = 16; off; off >>= 1)
            val += __shfl_xor_sync(0xffffffffu, val, off);
        if (lid == 0) red0[wid] = val;
        __syncthreads();
        if (t == 0) {
            float v = 0.0f;
            #pragma unroll
            for (int wI = 0; wI < 8; wI++) v += red0[wI];
            out[g] = fmaxf(v + b_out[0], 0.0f);
        }
    }
}

// ---------------------------------------------------------------------------
// inputs (metadata order):
//   0: x float32[N]  1: ei int32[2E]  2: batch int32[N]
//   3: W_l f32[256]  4: b_l f32[256]  5: W_out f32[256]  6: b_out f32[1]
// out: float32 [128]
// ---------------------------------------------------------------------------
extern "C" void kernel_launch(void* const* d_in, const int* in_sizes, int n_in,
                              void* d_out, int out_size) {
    const float* x     = (const float*)d_in[0];
    const int*   ei    = (const int*)d_in[1];
    const int*   batch = (const int*)d_in[2];
    const float* W_l   = (const float*)d_in[3];
    const float* b_l   = (const float*)d_in[4];
    const float* W_out = (const float*)d_in[5];
    const float* b_out = (const float*)d_in[6];
    float*       out   = (float*)d_out;

    const int N = in_sizes[0];
    const int E = in_sizes[1] / 2;

    // zero agg + completion counter via memset nodes
    void* aggp = nullptr;
    cudaGetSymbolAddress(&aggp, d_agg);
    cudaMemsetAsync(aggp, 0, (size_t)N * sizeof(float), 0);
    void* ctrp = nullptr;
    cudaGetSymbolAddress(&ctrp, d_ctr);
    cudaMemsetAsync(ctrp, 0, sizeof(int), 0);

    const int threads    = 256;
    const int edgeWork   = (E + 7) / 8;
    const int edgeBlocks = (edgeWork + threads - 1) / threads;
    const int bndThreads = (N + 3) / 4;
    const int bndBlocks  = (bndThreads + threads - 1) / threads;
    const int grid       = edgeBlocks + bndBlocks + 1 + NGRAPHS;

    fused_kernel<<<grid, threads>>>(ei, x, batch, W_l, b_l, W_out, b_out, out,
                                    E, N, edgeBlocks, bndBlocks);
}

// round 8
// speedup vs baseline: 1.3519x; 1.3519x over previous
#include <cuda_runtime.h>
#include <stdint.h>

#define NNODES   100000
#define NGRAPHS  128
#define HDIM     256

// Scratch (no allocation allowed)
__device__ float d_agg[NNODES];
__device__ int   d_starts[NGRAPHS + 1];

// ---------------------------------------------------------------------------
// Kernel A: edge scatter-add + boundary detection (independent work, fused
// into one grid; boundary rides free inside the LSU-bound edge scatter).
// ---------------------------------------------------------------------------
__global__ void edge_boundary_kernel(const int* __restrict__ ei,
                                     const float* __restrict__ x,
                                     const int* __restrict__ batch,
                                     int E, int N, int edgeBlocks) {
    const int bid = (int)blockIdx.x;
    if (bid < edgeBlocks) {
        // ---- edge scatter: 8 edges/thread, front-batched int4 index loads ----
        int t = bid * blockDim.x + threadIdx.x;
        int i = t << 3;
        if (i + 7 < E) {
            const int4* sp = reinterpret_cast<const int4*>(ei + i);
            const int4* dp = reinterpret_cast<const int4*>(ei + E + i);
            int4 s0 = __ldg(sp);
            int4 s1 = __ldg(sp + 1);
            int4 d0 = __ldg(dp);
            int4 d1 = __ldg(dp + 1);
            float v0 = __ldg(x + s0.x);
            float v1 = __ldg(x + s0.y);
            float v2 = __ldg(x + s0.z);
            float v3 = __ldg(x + s0.w);
            float v4 = __ldg(x + s1.x);
            float v5 = __ldg(x + s1.y);
            float v6 = __ldg(x + s1.z);
            float v7 = __ldg(x + s1.w);
            atomicAdd(&d_agg[d0.x], v0);
            atomicAdd(&d_agg[d0.y], v1);
            atomicAdd(&d_agg[d0.z], v2);
            atomicAdd(&d_agg[d0.w], v3);
            atomicAdd(&d_agg[d1.x], v4);
            atomicAdd(&d_agg[d1.y], v5);
            atomicAdd(&d_agg[d1.z], v6);
            atomicAdd(&d_agg[d1.w], v7);
        } else if (i < E) {
            for (int e = i; e < E; e++)
                atomicAdd(&d_agg[ei[E + e]], __ldg(x + ei[e]));
        }
    } else {
        // ---- boundary detection on sorted batch, 4 nodes/thread ----
        int t    = (bid - edgeBlocks) * blockDim.x + threadIdx.x;
        int base = t << 2;
        if (base >= N) return;
        int b0, b1, b2, b3;
        if (base + 3 < N) {
            int4 v = __ldg(reinterpret_cast<const int4*>(batch + base));
            b0 = v.x; b1 = v.y; b2 = v.z; b3 = v.w;
        } else {
            b0 = batch[base];
            b1 = (base + 1 < N) ? batch[base + 1] : b0;
            b2 = (base + 2 < N) ? batch[base + 2] : b1;
            b3 = (base + 3 < N) ? batch[base + 3] : b2;
        }
        int prev = (base == 0) ? -1 : __ldg(batch + base - 1);
        #pragma unroll
        for (int e = 0; e < 4; e++) {
            int idx = base + e;
            int b = (e == 0) ? b0 : (e == 1) ? b1 : (e == 2) ? b2 : b3;
            if (idx < N) {
                for (int g = prev + 1; g <= b; g++) d_starts[g] = idx;
                prev = b;
                if (idx == N - 1)
                    for (int g = b + 1; g <= NGRAPHS; g++) d_starts[g] = N;
            }
        }
    }
}

// ---------------------------------------------------------------------------
// Kernel B: one block per graph.  Prologue (weight-only, independent of
// kernel A) overlaps the primary kernel when launched with PDL; then
// cudaGridDependencySynchronize() gates the agg-dependent epilogue.
// Fast path uses float4 loads over the graph's contiguous agg range.
// ---------------------------------------------------------------------------
__global__ __launch_bounds__(HDIM)
void pool_kernel(const float* __restrict__ W_l,
                 const float* __restrict__ b_l,
                 const float* __restrict__ W_out,
                 const float* __restrict__ b_out,
                 float* __restrict__ out) {
    const int g = blockIdx.x;
    const int t = threadIdx.x;
    const int wid = t >> 5, lid = t & 31;

    // ---- prologue: weight-only work ----
    const float w  = W_l[t];
    const float b  = b_l[t];
    const float wo = W_out[t];
    const float bo = b_out[0];
    const int allz = __syncthreads_and(b == 0.0f);
    float p = (w > 0.0f) ? wo * w : 0.0f;
    float n = (w < 0.0f) ? wo * w : 0.0f;
    #pragma unroll
    for (int off = 16; off; off >>= 1) {
        p += __shfl_xor_sync(0xffffffffu, p, off);
        n += __shfl_xor_sync(0xffffffffu, n, off);
    }
    __shared__ float sp8[8], sn8[8];
    if (lid == 0) { sp8[wid] = p; sn8[wid] = n; }
    __syncthreads();
    float P = 0.0f, Nn = 0.0f;
    #pragma unroll
    for (int wI = 0; wI < 8; wI++) { P += sp8[wI]; Nn += sn8[wI]; }

    // ---- wait for primary kernel (no-op if not launched via PDL) ----
    cudaGridDependencySynchronize();

    const int start = d_starts[g];
    const int end   = d_starts[g + 1];
    const int len   = end - start;
    const float cnt = fmaxf((float)len, 1.0f);

    __shared__ float red0[8], red1[8];

    if (allz) {
        // fast path: relu(v*w) sums collapse to two slopes over sign(v).
        // float4 main loop over the 16B-aligned interior, scalar peel/tail.
        float sp = 0.0f, sn = 0.0f;
        const int a0 = (start + 3) & ~3;            // first 16B-aligned idx
        const int a1 = end & ~3;                    // end of aligned region
        // peel head + tail (at most 3 each) with the first threads
        if (t < 4) {
            int hi = start + t;
            if (hi < a0 && hi < end) {
                float v = d_agg[hi];
                sp += fmaxf(v, 0.0f);
                sn += fminf(v, 0.0f);
            }
            int ti = (a1 > a0 ? a1 : end > a0 ? a0 : end) + t;  // tail base
            ti = ((a1 > a0) ? a1 : a0) + t;
            if (ti >= end) ti = -1;
            if (ti >= 0 && a1 > a0) {
                float v = d_agg[ti];
                sp += fmaxf(v, 0.0f);
                sn += fminf(v, 0.0f);
            } else if (a1 <= a0) {
                // tiny graph entirely in peel: handled above when hi<end
            }
        }
        if (a1 > a0) {
            const float4* va = reinterpret_cast<const float4*>(d_agg + a0);
            const int nv = (a1 - a0) >> 2;          // number of float4
            for (int i = t; i < nv; i += HDIM) {
                float4 v = va[i];
                sp += fmaxf(v.x, 0.0f) + fmaxf(v.y, 0.0f)
                    + fmaxf(v.z, 0.0f) + fmaxf(v.w, 0.0f);
                sn += fminf(v.x, 0.0f) + fminf(v.y, 0.0f)
                    + fminf(v.z, 0.0f) + fminf(v.w, 0.0f);
            }
        }
        #pragma unroll
        for (int off = 16; off; off >>= 1) {
            sp += __shfl_xor_sync(0xffffffffu, sp, off);
            sn += __shfl_xor_sync(0xffffffffu, sn, off);
        }
        if (lid == 0) { red0[wid] = sp; red1[wid] = sn; }
        __syncthreads();
        if (t == 0) {
            float SP = 0.0f, SN = 0.0f;
            #pragma unroll
            for (int wI = 0; wI < 8; wI++) { SP += red0[wI]; SN += red1[wI]; }
            out[g] = fmaxf((P * SP + Nn * SN) / cnt + bo, 0.0f);
        }
        return;
    }

    // exact slow path (general b_l): one thread per feature
    float acc = 0.0f;
    __shared__ float sa[HDIM];
    for (int base = start; base < end; base += HDIM) {
        int nn = min(HDIM, end - base);
        __syncthreads();
        if (t < nn) sa[t] = d_agg[base + t];
        __syncthreads();
        float q0 = 0.f, q1 = 0.f, q2 = 0.f, q3 = 0.f;
        int j = 0;
        for (; j + 3 < nn; j += 4) {
            q0 += fmaxf(fmaf(sa[j],     w, b), 0.0f);
            q1 += fmaxf(fmaf(sa[j + 1], w, b), 0.0f);
            q2 += fmaxf(fmaf(sa[j + 2], w, b), 0.0f);
            q3 += fmaxf(fmaf(sa[j + 3], w, b), 0.0f);
        }
        for (; j < nn; j++)
            q0 += fmaxf(fmaf(sa[j], w, b), 0.0f);
        acc += (q0 + q1) + (q2 + q3);
    }
    float val = acc * wo / cnt;
    #pragma unroll
    for (int off = 16; off; off >>= 1)
        val += __shfl_xor_sync(0xffffffffu, val, off);
    if (lid == 0) red0[wid] = val;
    __syncthreads();
    if (t == 0) {
        float v = 0.0f;
        #pragma unroll
        for (int wI = 0; wI < 8; wI++) v += red0[wI];
        out[g] = fmaxf(v + bo, 0.0f);
    }
}

// ---------------------------------------------------------------------------
// inputs (metadata order):
//   0: x float32[N]  1: ei int32[2E]  2: batch int32[N]
//   3: W_l f32[256]  4: b_l f32[256]  5: W_out f32[256]  6: b_out f32[1]
// out: float32 [128]
// ---------------------------------------------------------------------------
extern "C" void kernel_launch(void* const* d_in, const int* in_sizes, int n_in,
                              void* d_out, int out_size) {
    const float* x     = (const float*)d_in[0];
    const int*   ei    = (const int*)d_in[1];
    const int*   batch = (const int*)d_in[2];
    const float* W_l   = (const float*)d_in[3];
    const float* b_l   = (const float*)d_in[4];
    const float* W_out = (const float*)d_in[5];
    const float* b_out = (const float*)d_in[6];
    float*       out   = (float*)d_out;

    const int N = in_sizes[0];
    const int E = in_sizes[1] / 2;

    // zero agg via memset node
    void* aggp = nullptr;
    cudaGetSymbolAddress(&aggp, d_agg);
    cudaMemsetAsync(aggp, 0, (size_t)N * sizeof(float), 0);

    const int threads    = 256;
    const int edgeWork   = (E + 7) / 8;
    const int edgeBlocks = (edgeWork + threads - 1) / threads;
    const int bndThreads = (N + 3) / 4;
    const int bndBlocks  = (bndThreads + threads - 1) / threads;

    edge_boundary_kernel<<<edgeBlocks + bndBlocks, threads>>>(
        ei, x, batch, E, N, edgeBlocks);

    // Pool with programmatic dependent launch (prologue overlaps primary);
    // on ANY failure fall back to a plain launch (stream order still correct,
    // cudaGridDependencySynchronize is a no-op outside PDL).
    cudaError_t lerr = cudaErrorUnknown;
    {
        cudaLaunchConfig_t cfg = {};
        cfg.gridDim  = dim3(NGRAPHS, 1, 1);
        cfg.blockDim = dim3(HDIM, 1, 1);
        cfg.dynamicSmemBytes = 0;
        cfg.stream = 0;
        cudaLaunchAttribute attrs[1];
        attrs[0].id = cudaLaunchAttributeProgrammaticStreamSerialization;
        attrs[0].val.programmaticStreamSerializationAllowed = 1;
        cfg.attrs = attrs;
        cfg.numAttrs = 1;
        lerr = cudaLaunchKernelEx(&cfg, pool_kernel, W_l, b_l, W_out, b_out, out);
    }
    if (lerr != cudaSuccess) {
        (void)cudaGetLastError();   // clear sticky error, then plain launch
        pool_kernel<<<NGRAPHS, HDIM>>>(W_l, b_l, W_out, b_out, out);
    }
}